// round 6
// baseline (speedup 1.0000x reference)
#include <cuda_runtime.h>
#include <cuda_fp16.h>
#include <math.h>
#include <float.h>

// ---------------- problem constants ----------------
#define NN      50000
#define NE      600000
#define DD      128
#define NET     4
#define NSTEPS  5
#define NHEADS  2
#define NG      64
#define NCLS    32

// ---------------- device scratch ----------------
__device__ __half g_h_h[NN * DD];                 // node state (fp16)
__device__ __half g_s_h[(size_t)NN * NET * DD];   // per-etype segment sums of h
__device__ float  g_cnt[NN * NET];                // per-(node,etype) edge counts
__device__ __half g_a_h[NN * DD];                 // aggregated+transformed messages
__device__ __half g_gh_h [NN * 3 * DD];           // GRU hidden gates
__device__ __half g_gi_h [NN * 3 * DD];           // GRU input gates
__device__ __half g_zft_h[NN * NHEADS * DD];      // GAT features
__device__ float  g_el [NN * NHEADS];
__device__ float  g_er [NN * NHEADS];
__device__ float  g_rst[NN * NHEADS * DD];
__device__ float  g_logits[2][NG * NHEADS * NCLS];

// fp16 weights (converted once per launch)
__device__ __half g_Wcat_h[DD * NET * DD];  // [o][k*128+d] = W_et[k][o][d]
__device__ __half g_Whh_h[3 * DD * DD];
__device__ __half g_Wih_h[3 * DD * DD];
__device__ __half g_Wfc_h[NHEADS * DD * DD];

__device__ int g_deg   [NN];
__device__ int g_indptr[NN + 1];
__device__ int g_cursor[NN];
__device__ int g_eids  [NE];
__device__ int g_gs    [NG + 1];
__device__ int g_bsum  [64];

__device__ __forceinline__ float sigf(float x) { return 1.f / (1.f + expf(-x)); }

__device__ __forceinline__ float4 h4tof4(uint2 v) {
    float2 a = __half22float2(*(__half2*)&v.x);
    float2 b = __half22float2(*(__half2*)&v.y);
    return make_float4(a.x, a.y, b.x, b.y);
}
__device__ __forceinline__ uint2 f4toh4(float4 v) {
    uint2 o;
    *(__half2*)&o.x = __floats2half2_rn(v.x, v.y);
    *(__half2*)&o.y = __floats2half2_rn(v.z, v.w);
    return o;
}

// ---------------- misc small kernels ----------------
__global__ void conv_w(const float* __restrict__ src, __half* __restrict__ dst, int n) {
    int i = blockIdx.x * blockDim.x + threadIdx.x;
    if (i < n / 2) {
        float2 v = ((const float2*)src)[i];
        ((__half2*)dst)[i] = __floats2half2_rn(v.x, v.y);
    }
}

// W_cat[o][k*128+d] = W_et[k*16384 + o*128 + d]
__global__ void conv_wcat(const float* __restrict__ W_et) {
    int j = blockIdx.x * blockDim.x + threadIdx.x;
    if (j < DD * NET * DD) {
        int o = j >> 9, rem = j & 511, k = rem >> 7, d = rem & 127;
        g_Wcat_h[j] = __float2half(W_et[k * (DD * DD) + o * DD + d]);
    }
}

__global__ void copy_h(const float* __restrict__ f) {
    int i = blockIdx.x * blockDim.x + threadIdx.x;
    if (i < NN * (DD / 4)) {
        float4 v = ((const float4*)f)[i];
        ((uint2*)g_h_h)[i] = f4toh4(v);
    }
}

__global__ void zero_deg() {
    int i = blockIdx.x * blockDim.x + threadIdx.x;
    if (i < NN) g_deg[i] = 0;
}

__global__ void count_deg(const int* __restrict__ dst) {
    int e = blockIdx.x * blockDim.x + threadIdx.x;
    if (e < NE) atomicAdd(&g_deg[dst[e]], 1);
}

// ---- multi-block scan: 49 blocks x 1024 ----
__global__ void scan1() {
    __shared__ int wsum[32];
    int tid = threadIdx.x;
    int i = blockIdx.x * 1024 + tid;
    int v = (i < NN) ? g_deg[i] : 0;
    int x = v;
    #pragma unroll
    for (int o = 1; o < 32; o <<= 1) {
        int y = __shfl_up_sync(0xffffffffu, x, o);
        if ((tid & 31) >= o) x += y;
    }
    if ((tid & 31) == 31) wsum[tid >> 5] = x;
    __syncthreads();
    if (tid < 32) {
        int wv = wsum[tid];
        int xs = wv;
        #pragma unroll
        for (int o = 1; o < 32; o <<= 1) {
            int y = __shfl_up_sync(0xffffffffu, xs, o);
            if (tid >= o) xs += y;
        }
        wsum[tid] = xs - wv;
    }
    __syncthreads();
    int excl = (x - v) + wsum[tid >> 5];
    if (i < NN) g_indptr[i] = excl;
    if (tid == 1023) g_bsum[blockIdx.x] = excl + v;
}

__global__ void scan2() {
    int s = 0;
    for (int b = 0; b < 49; b++) { int t = g_bsum[b]; g_bsum[b] = s; s += t; }
    g_indptr[NN] = s;
}

__global__ void scan3() {
    int i = blockIdx.x * 1024 + threadIdx.x;
    if (i < NN) {
        int v = g_indptr[i] + g_bsum[blockIdx.x];
        g_indptr[i] = v;
        g_cursor[i] = v;
    }
}

__global__ void build_eids(const int* __restrict__ dst) {
    int e = blockIdx.x * blockDim.x + threadIdx.x;
    if (e < NE) {
        int p = atomicAdd(&g_cursor[dst[e]], 1);
        g_eids[p] = e;
    }
}

// ---------------- per-etype segment sum of h (gathers from L2-hot h) ----------------
__global__ void aggregate4(const int* __restrict__ src, const int* __restrict__ et) {
    int w = (blockIdx.x * blockDim.x + threadIdx.x) >> 5;
    if (w >= NN) return;
    int lane = threadIdx.x & 31;
    int s0 = g_indptr[w], s1 = g_indptr[w + 1];
    float4 a0 = make_float4(0.f,0.f,0.f,0.f), a1 = a0, a2 = a0, a3 = a0;
    float c0 = 0.f, c1 = 0.f, c2 = 0.f, c3 = 0.f;
    for (int p = s0; p < s1; p++) {
        int e = g_eids[p];
        int s = src[e];
        int k = et[e];
        float4 f = h4tof4(((const uint2*)(g_h_h + (size_t)s * DD))[lane]);
        if (k == 0)      { a0.x+=f.x; a0.y+=f.y; a0.z+=f.z; a0.w+=f.w; c0+=1.f; }
        else if (k == 1) { a1.x+=f.x; a1.y+=f.y; a1.z+=f.z; a1.w+=f.w; c1+=1.f; }
        else if (k == 2) { a2.x+=f.x; a2.y+=f.y; a2.z+=f.z; a2.w+=f.w; c2+=1.f; }
        else             { a3.x+=f.x; a3.y+=f.y; a3.z+=f.z; a3.w+=f.w; c3+=1.f; }
    }
    uint2* sp = (uint2*)(g_s_h + (size_t)w * (NET * DD));
    sp[lane]      = f4toh4(a0);
    sp[32 + lane] = f4toh4(a1);
    sp[64 + lane] = f4toh4(a2);
    sp[96 + lane] = f4toh4(a3);
    if (lane == 0)
        *(float4*)(g_cnt + w * NET) = make_float4(c0, c1, c2, c3);
}

// ---------------- FP16 tensor-core GEMM ----------------
// C(half)[n, col] = sum_d A[n,d]*Bw[col,d] (+ bias); fp32 accum, m16n8k16.
// Block 128x128 tile; K loop in 128-superchunks, each staged via 2 cp.async groups.
#define S2 68
#define TILE_H2 (128 * S2)

// biasMode: 0 = none, 1 = bias[col], 2 = sum_k cnt[row][k]*bet[k*128+col]
__device__ __forceinline__ void gemm_body(
    const __half* __restrict__ A, const __half* __restrict__ Bw,
    __half* __restrict__ C, int kDim, int outDim, int rowBase, int colBase,
    int biasMode, const float* __restrict__ bias,
    __half2* As2, __half2* Bs2)
{
    const int tid = threadIdx.x;
    const int lane = tid & 31, wid = tid >> 5;
    const int wm = wid >> 2, wn = wid & 3;
    const int g8 = lane >> 2, t4 = lane & 3;

    float c[4][4][4];
    #pragma unroll
    for (int mt = 0; mt < 4; mt++)
        #pragma unroll
        for (int nt = 0; nt < 4; nt++)
            #pragma unroll
            for (int i = 0; i < 4; i++) c[mt][nt][i] = 0.f;

    const int lr = tid >> 1;
    const int lh2 = (tid & 1) * 16;
    const int ga = rowBase + lr;
    const int aBytes = (ga < NN) ? 16 : 0;
    const __half* Ap = A + (size_t)ga * kDim;
    const __half* Bp = Bw + (size_t)(colBase + lr) * kDim;
    const unsigned aDst = (unsigned)__cvta_generic_to_shared(&As2[lr * S2 + lh2]);
    const unsigned bDst = (unsigned)__cvta_generic_to_shared(&Bs2[lr * S2 + lh2]);

    for (int kb0 = 0; kb0 < kDim; kb0 += 128) {
        if (kb0) __syncthreads();
        #pragma unroll
        for (int ch = 0; ch < 2; ch++) {
            #pragma unroll
            for (int i = 0; i < 4; i++) {
                asm volatile("cp.async.cg.shared.global [%0], [%1], 16, %2;"
                    :: "r"(aDst + ch * 128 + i * 16),
                       "l"(Ap + kb0 + ch * 64 + lh2 * 2 + i * 8), "r"(aBytes));
                asm volatile("cp.async.cg.shared.global [%0], [%1], 16;"
                    :: "r"(bDst + ch * 128 + i * 16),
                       "l"(Bp + kb0 + ch * 64 + lh2 * 2 + i * 8));
            }
            asm volatile("cp.async.commit_group;");
        }
        #pragma unroll
        for (int ch = 0; ch < 2; ch++) {
            if (ch == 0) asm volatile("cp.async.wait_group 1;");
            else         asm volatile("cp.async.wait_group 0;");
            __syncthreads();
            #pragma unroll
            for (int ks = 0; ks < 4; ks++) {
                const int kb = ch * 32 + ks * 8;
                unsigned af[4][4], bf[4][2];
                #pragma unroll
                for (int mt = 0; mt < 4; mt++) {
                    int r0 = wm * 64 + mt * 16 + g8;
                    af[mt][0] = *(unsigned*)&As2[r0 * S2 + kb + t4];
                    af[mt][1] = *(unsigned*)&As2[(r0 + 8) * S2 + kb + t4];
                    af[mt][2] = *(unsigned*)&As2[r0 * S2 + kb + 4 + t4];
                    af[mt][3] = *(unsigned*)&As2[(r0 + 8) * S2 + kb + 4 + t4];
                }
                #pragma unroll
                for (int nt = 0; nt < 4; nt++) {
                    int n0 = wn * 32 + nt * 8 + g8;
                    bf[nt][0] = *(unsigned*)&Bs2[n0 * S2 + kb + t4];
                    bf[nt][1] = *(unsigned*)&Bs2[n0 * S2 + kb + 4 + t4];
                }
                #pragma unroll
                for (int mt = 0; mt < 4; mt++)
                    #pragma unroll
                    for (int nt = 0; nt < 4; nt++) {
                        asm volatile(
                            "mma.sync.aligned.m16n8k16.row.col.f32.f16.f16.f32 "
                            "{%0,%1,%2,%3}, {%4,%5,%6,%7}, {%8,%9}, {%0,%1,%2,%3};\n"
                            : "+f"(c[mt][nt][0]), "+f"(c[mt][nt][1]),
                              "+f"(c[mt][nt][2]), "+f"(c[mt][nt][3])
                            : "r"(af[mt][0]), "r"(af[mt][1]), "r"(af[mt][2]), "r"(af[mt][3]),
                              "r"(bf[nt][0]), "r"(bf[nt][1]));
                    }
            }
        }
    }

    // epilogue
    #pragma unroll
    for (int nt = 0; nt < 4; nt++) {
        int col = colBase + wn * 32 + nt * 8 + 2 * t4;
        float b0 = 0.f, b1 = 0.f;
        float bet0[4], bet1[4];
        if (biasMode == 1) { b0 = bias[col]; b1 = bias[col + 1]; }
        else if (biasMode == 2) {
            #pragma unroll
            for (int k = 0; k < 4; k++) {
                bet0[k] = bias[k * 128 + col];
                bet1[k] = bias[k * 128 + col + 1];
            }
        }
        #pragma unroll
        for (int mt = 0; mt < 4; mt++) {
            int r0 = rowBase + wm * 64 + mt * 16 + g8;
            if (biasMode == 2) {
                if (r0 < NN) {
                    float4 cr = *(const float4*)(g_cnt + r0 * NET);
                    float bb0 = cr.x*bet0[0] + cr.y*bet0[1] + cr.z*bet0[2] + cr.w*bet0[3];
                    float bb1 = cr.x*bet1[0] + cr.y*bet1[1] + cr.z*bet1[2] + cr.w*bet1[3];
                    *(__half2*)(C + (size_t)r0 * outDim + col) =
                        __floats2half2_rn(c[mt][nt][0] + bb0, c[mt][nt][1] + bb1);
                }
                if (r0 + 8 < NN) {
                    float4 cr = *(const float4*)(g_cnt + (r0 + 8) * NET);
                    float bb0 = cr.x*bet0[0] + cr.y*bet0[1] + cr.z*bet0[2] + cr.w*bet0[3];
                    float bb1 = cr.x*bet1[0] + cr.y*bet1[1] + cr.z*bet1[2] + cr.w*bet1[3];
                    *(__half2*)(C + (size_t)(r0 + 8) * outDim + col) =
                        __floats2half2_rn(c[mt][nt][2] + bb0, c[mt][nt][3] + bb1);
                }
            } else {
                if (r0 < NN)
                    *(__half2*)(C + (size_t)r0 * outDim + col) =
                        __floats2half2_rn(c[mt][nt][0] + b0, c[mt][nt][1] + b1);
                if (r0 + 8 < NN)
                    *(__half2*)(C + (size_t)(r0 + 8) * outDim + col) =
                        __floats2half2_rn(c[mt][nt][2] + b0, c[mt][nt][3] + b1);
            }
        }
    }
}

// mode 0: a = s @ W_cat^T + cnt-weighted b_et   (K=512, 1 col tile)
// mode 1: fused gh (y<3, A=h) + gi (y>=3, A=a)  (K=128)
// mode 2: zft = h @ W_fc^T                      (K=128, 2 col tiles)
__global__ __launch_bounds__(256, 2)
void gemm_all(int mode, const float* __restrict__ b0, const float* __restrict__ b1) {
    extern __shared__ __half2 sm2[];
    __half2* As2 = sm2;
    __half2* Bs2 = sm2 + TILE_H2;
    int y = blockIdx.y;
    if (mode == 0) {
        gemm_body(g_s_h, g_Wcat_h, g_a_h, 512, 128, blockIdx.x * 128, 0, 2, b0, As2, Bs2);
    } else if (mode == 1) {
        if (y < 3)
            gemm_body(g_h_h, g_Whh_h, g_gh_h, 128, 384, blockIdx.x * 128, y * 128, 1, b0, As2, Bs2);
        else
            gemm_body(g_a_h, g_Wih_h, g_gi_h, 128, 384, blockIdx.x * 128, (y - 3) * 128, 1, b1, As2, Bs2);
    } else {
        gemm_body(g_h_h, g_Wfc_h, g_zft_h, 128, 256, blockIdx.x * 128, y * 128, 0, nullptr, As2, Bs2);
    }
}

// ---------------- GRU elementwise update (fp16 everything) ----------------
__global__ void gru_update() {
    int idx = blockIdx.x * blockDim.x + threadIdx.x;
    if (idx >= NN * 32) return;
    int n = idx >> 5, q = idx & 31;
    const __half* gip = g_gi_h + (size_t)n * 384 + q * 4;
    const __half* ghp = g_gh_h + (size_t)n * 384 + q * 4;
    float4 ir = h4tof4(*(const uint2*)gip);
    float4 iz = h4tof4(*(const uint2*)(gip + 128));
    float4 inn = h4tof4(*(const uint2*)(gip + 256));
    float4 hr = h4tof4(*(const uint2*)ghp);
    float4 hz = h4tof4(*(const uint2*)(ghp + 128));
    float4 hn = h4tof4(*(const uint2*)(ghp + 256));
    uint2* hp = (uint2*)(g_h_h + (size_t)n * 128);
    float4 h = h4tof4(hp[q]);
    float4 o;
    {
        float r = sigf(ir.x + hr.x), z = sigf(iz.x + hz.x);
        float nn2 = tanhf(inn.x + r * hn.x);
        o.x = (1.f - z) * nn2 + z * h.x;
    }
    {
        float r = sigf(ir.y + hr.y), z = sigf(iz.y + hz.y);
        float nn2 = tanhf(inn.y + r * hn.y);
        o.y = (1.f - z) * nn2 + z * h.y;
    }
    {
        float r = sigf(ir.z + hr.z), z = sigf(iz.z + hz.z);
        float nn2 = tanhf(inn.z + r * hn.z);
        o.z = (1.f - z) * nn2 + z * h.z;
    }
    {
        float r = sigf(ir.w + hr.w), z = sigf(iz.w + hz.w);
        float nn2 = tanhf(inn.w + r * hn.w);
        o.w = (1.f - z) * nn2 + z * h.w;
    }
    hp[q] = f4toh4(o);
}

// ---------------- row L2-normalize + sigmoid (fp16 h) ----------------
__global__ void norm_sigmoid() {
    int w = (blockIdx.x * blockDim.x + threadIdx.x) >> 5;
    if (w >= NN) return;
    int lane = threadIdx.x & 31;
    uint2* p = (uint2*)(g_h_h + (size_t)w * 128);
    float4 v = h4tof4(p[lane]);
    float ss = v.x * v.x + v.y * v.y + v.z * v.z + v.w * v.w;
    #pragma unroll
    for (int o = 16; o; o >>= 1) ss += __shfl_xor_sync(0xffffffffu, ss, o);
    float inv = 1.f / fmaxf(sqrtf(ss), 1e-12f);
    v.x = sigf(v.x * inv); v.y = sigf(v.y * inv);
    v.z = sigf(v.z * inv); v.w = sigf(v.w * inv);
    p[lane] = f4toh4(v);
}

// ---------------- GAT attention scalars el/er ----------------
__global__ void elr_kernel(const float* __restrict__ al, const float* __restrict__ ar) {
    int w = (blockIdx.x * blockDim.x + threadIdx.x) >> 5;
    if (w >= NN) return;
    int lane = threadIdx.x & 31;
    const uint2* z2 = (const uint2*)(g_zft_h + (size_t)w * 256);
    const float4* al4 = (const float4*)al;
    const float4* ar4 = (const float4*)ar;
    #pragma unroll
    for (int hd = 0; hd < 2; hd++) {
        float4 zv = h4tof4(z2[hd * 32 + lane]);
        float4 lv = al4[hd * 32 + lane];
        float4 rv = ar4[hd * 32 + lane];
        float pl = zv.x * lv.x + zv.y * lv.y + zv.z * lv.z + zv.w * lv.w;
        float pr = zv.x * rv.x + zv.y * rv.y + zv.z * rv.z + zv.w * rv.w;
        #pragma unroll
        for (int o = 16; o; o >>= 1) {
            pl += __shfl_xor_sync(0xffffffffu, pl, o);
            pr += __shfl_xor_sync(0xffffffffu, pr, o);
        }
        if (lane == 0) { g_el[w * 2 + hd] = pl; g_er[w * 2 + hd] = pr; }
    }
}

// ---------------- fused GAT: softmax (shift-free) + weighted accum + bias + relu ----------------
__global__ void gat_fused(const int* __restrict__ src, const float* __restrict__ gbias) {
    int w = (blockIdx.x * blockDim.x + threadIdx.x) >> 5;
    if (w >= NN) return;
    int lane = threadIdx.x & 31;
    int s0 = g_indptr[w], s1 = g_indptr[w + 1];
    float2 erd = ((const float2*)g_er)[w];
    float4 a0 = make_float4(0.f,0.f,0.f,0.f), a1 = a0;
    float den0 = 0.f, den1 = 0.f;
    for (int p = s0; p < s1; p++) {
        int e = g_eids[p];
        int s = src[e];
        float w0 = 0.f, w1 = 0.f;
        if (lane == 0) {
            float2 els = ((const float2*)g_el)[s];
            float e0 = els.x + erd.x; e0 = e0 > 0.f ? e0 : 0.2f * e0;
            float e1 = els.y + erd.y; e1 = e1 > 0.f ? e1 : 0.2f * e1;
            w0 = expf(e0); w1 = expf(e1);
        }
        w0 = __shfl_sync(0xffffffffu, w0, 0);
        w1 = __shfl_sync(0xffffffffu, w1, 0);
        den0 += w0; den1 += w1;
        const uint2* z2 = (const uint2*)(g_zft_h + (size_t)s * 256);
        float4 z0 = h4tof4(z2[lane]), z1 = h4tof4(z2[32 + lane]);
        a0.x += w0 * z0.x; a0.y += w0 * z0.y; a0.z += w0 * z0.z; a0.w += w0 * z0.w;
        a1.x += w1 * z1.x; a1.y += w1 * z1.y; a1.z += w1 * z1.z; a1.w += w1 * z1.w;
    }
    float i0 = (den0 > 0.f) ? 1.f / den0 : 0.f;
    float i1 = (den1 > 0.f) ? 1.f / den1 : 0.f;
    const float4* b4 = (const float4*)gbias;
    float4 b0 = b4[lane], b1 = b4[32 + lane];
    float4 o0, o1;
    o0.x = fmaxf(a0.x * i0 + b0.x, 0.f); o0.y = fmaxf(a0.y * i0 + b0.y, 0.f);
    o0.z = fmaxf(a0.z * i0 + b0.z, 0.f); o0.w = fmaxf(a0.w * i0 + b0.w, 0.f);
    o1.x = fmaxf(a1.x * i1 + b1.x, 0.f); o1.y = fmaxf(a1.y * i1 + b1.y, 0.f);
    o1.z = fmaxf(a1.z * i1 + b1.z, 0.f); o1.w = fmaxf(a1.w * i1 + b1.w, 0.f);
    float4* outp = (float4*)(g_rst + (size_t)w * 256);
    outp[lane] = o0;
    outp[32 + lane] = o1;
}

// ---------------- graph bounds ----------------
__global__ void graph_bounds(const int* __restrict__ gid) {
    int b = threadIdx.x;
    if (b > NG) return;
    if (b == NG) { g_gs[NG] = NN; return; }
    int lo = 0, hi = NN;
    while (lo < hi) {
        int mid = (lo + hi) >> 1;
        if (gid[mid] < b) lo = mid + 1; else hi = mid;
    }
    g_gs[b] = lo;
}

// ---------------- mean pool + classify ----------------
__global__ void pool_classify(const float* __restrict__ Wc, const float* __restrict__ bc, int gidx) {
    __shared__ float sh[256];
    int b = blockIdx.x;
    int t = threadIdx.x;
    int s = g_gs[b], e2 = g_gs[b + 1];
    float sum = 0.f;
    for (int r = s; r < e2; r++) sum += g_rst[(size_t)r * 256 + t];
    sh[t] = sum / fmaxf((float)(e2 - s), 1.f);
    __syncthreads();
    if (t < 64) {
        int hd = t >> 5, c = t & 31;
        float acc = bc[c];
        const float* hp = sh + hd * 128;
        const float* wp = Wc + c * 128;
        #pragma unroll 8
        for (int d2 = 0; d2 < 128; d2++) acc += hp[d2] * wp[d2];
        g_logits[gidx][(b * 2 + hd) * 32 + c] = acc;
    }
}

// ---------------- final distance + head softmax ----------------
__global__ void final_kernel(float* __restrict__ out) {
    int b = threadIdx.x;
    if (b >= NG) return;
    float dv[2];
    #pragma unroll
    for (int hd = 0; hd < 2; hd++) {
        float ss = 0.f;
        #pragma unroll
        for (int c = 0; c < 32; c++) {
            float df = g_logits[0][(b * 2 + hd) * 32 + c]
                     - g_logits[1][(b * 2 + hd) * 32 + c] + 1e-6f;
            ss += df * df;
        }
        dv[hd] = sqrtf(ss);
    }
    float mx = fmaxf(dv[0], dv[1]);
    float e0 = expf(dv[0] - mx), e1 = expf(dv[1] - mx);
    float inv = 1.f / (e0 + e1);
    out[b * 2] = e0 * inv;
    out[b * 2 + 1] = e1 * inv;
}

// ---------------- host driver ----------------
extern "C" void kernel_launch(void* const* d_in, const int* in_sizes, int n_in,
                              void* d_out, int out_size) {
    const float* in1  = (const float*)d_in[0];
    const float* in2  = (const float*)d_in[1];
    const int* src1 = (const int*)d_in[2];
    const int* dst1 = (const int*)d_in[3];
    const int* et1  = (const int*)d_in[4];
    const int* gid1 = (const int*)d_in[5];
    const int* src2 = (const int*)d_in[6];
    const int* dst2 = (const int*)d_in[7];
    const int* et2  = (const int*)d_in[8];
    const int* gid2 = (const int*)d_in[9];
    const float* W_et  = (const float*)d_in[10];
    const float* b_et  = (const float*)d_in[11];
    const float* W_ih  = (const float*)d_in[12];
    const float* W_hh  = (const float*)d_in[13];
    const float* b_ih  = (const float*)d_in[14];
    const float* b_hh  = (const float*)d_in[15];
    const float* W_fc  = (const float*)d_in[16];
    const float* al    = (const float*)d_in[17];
    const float* ar    = (const float*)d_in[18];
    const float* gb    = (const float*)d_in[19];
    const float* W_cls = (const float*)d_in[20];
    const float* b_cls = (const float*)d_in[21];

    const int SMEM = 2 * TILE_H2 * 4;
    static int attr_done = 0;
    if (!attr_done) {
        cudaFuncSetAttribute(gemm_all, cudaFuncAttributeMaxDynamicSharedMemorySize, SMEM);
        attr_done = 1;
    }

    // weight conversion (once per launch)
    {
        __half* p1; cudaGetSymbolAddress((void**)&p1, g_Whh_h);
        __half* p2; cudaGetSymbolAddress((void**)&p2, g_Wih_h);
        __half* p3; cudaGetSymbolAddress((void**)&p3, g_Wfc_h);
        conv_wcat<<<(DD * NET * DD + 255) / 256, 256>>>(W_et);
        conv_w<<<(3 * DD * DD / 2 + 255) / 256, 256>>>(W_hh, p1, 3 * DD * DD);
        conv_w<<<(3 * DD * DD / 2 + 255) / 256, 256>>>(W_ih, p2, 3 * DD * DD);
        conv_w<<<(NHEADS * DD * DD / 2 + 255) / 256, 256>>>(W_fc, p3, NHEADS * DD * DD);
    }

    const int NBLK_E = (NE + 255) / 256;
    const int NBLK_N = (NN + 255) / 256;
    const int NBLK_W = NN / 8;
    const dim3 gA(391, 1), gBC(391, 6), gZ(391, 2);

    for (int g = 0; g < 2; g++) {
        const float* feat = g ? in2 : in1;
        const int* src = g ? src2 : src1;
        const int* dst = g ? dst2 : dst1;
        const int* et  = g ? et2 : et1;
        const int* gid = g ? gid2 : gid1;

        copy_h<<<(NN * 32 + 255) / 256, 256>>>(feat);
        zero_deg<<<NBLK_N, 256>>>();
        count_deg<<<NBLK_E, 256>>>(dst);
        scan1<<<49, 1024>>>();
        scan2<<<1, 1>>>();
        scan3<<<49, 1024>>>();
        build_eids<<<NBLK_E, 256>>>(dst);

        for (int s = 0; s < NSTEPS; s++) {
            aggregate4<<<NBLK_W, 256>>>(src, et);
            gemm_all<<<gA, 256, SMEM>>>(0, b_et, nullptr);
            gemm_all<<<gBC, 256, SMEM>>>(1, b_hh, b_ih);
            gru_update<<<(NN * 32 + 255) / 256, 256>>>();
        }
        norm_sigmoid<<<NBLK_W, 256>>>();
        gemm_all<<<gZ, 256, SMEM>>>(2, nullptr, nullptr);
        elr_kernel<<<NBLK_W, 256>>>(al, ar);
        gat_fused<<<NBLK_W, 256>>>(src, gb);
        graph_bounds<<<1, NG + 1>>>(gid);
        pool_classify<<<NG, 256>>>(W_cls, b_cls, g);
    }
    final_kernel<<<1, NG>>>((float*)d_out);
}

// round 7
// speedup vs baseline: 1.1462x; 1.1462x over previous
#include <cuda_runtime.h>
#include <cuda_fp16.h>
#include <math.h>
#include <float.h>

// ---------------- problem constants ----------------
#define NN      50000
#define NE      600000
#define DD      128
#define NET     4
#define NSTEPS  5
#define NHEADS  2
#define NG      64
#define NCLS    32

// ---------------- device scratch ----------------
__device__ __half g_h_h[NN * DD];                 // node state (fp16)
__device__ __half g_a_h[NN * DD];                 // aggregated messages (fp16)
__device__ __half g_t_h  [(size_t)NN * NET * DD]; // per-etype transform (fp16)
__device__ __half g_gh_h [NN * 3 * DD];           // GRU hidden gates
__device__ __half g_gi_h [NN * 3 * DD];           // GRU input gates
__device__ __half g_zft_h[NN * NHEADS * DD];      // GAT features
__device__ float  g_el [NN * NHEADS];
__device__ float  g_er [NN * NHEADS];
__device__ float  g_wgt[NE * NHEADS];             // CSR-ordered edge softmax weights
__device__ float  g_rst[NN * NHEADS * DD];
__device__ float  g_logits[2][NG * NHEADS * NCLS];

// fp16 weights (converted once per launch)
__device__ __half g_Wet_h[NET * DD * DD];
__device__ __half g_Whh_h[3 * DD * DD];
__device__ __half g_Wih_h[3 * DD * DD];
__device__ __half g_Wfc_h[NHEADS * DD * DD];

__device__ int g_deg   [NN];
__device__ int g_indptr[NN + 1];
__device__ int g_cursor[NN];
__device__ int g_pk    [NE];   // CSR-ordered packed src | (etype<<16)
__device__ int g_epos  [NE];   // edge -> CSR slot
__device__ int g_gs    [NG + 1];
__device__ int g_bsum  [64];

__device__ __forceinline__ float sigf(float x) { return 1.f / (1.f + expf(-x)); }

__device__ __forceinline__ float4 h4tof4(uint2 v) {
    float2 a = __half22float2(*(__half2*)&v.x);
    float2 b = __half22float2(*(__half2*)&v.y);
    return make_float4(a.x, a.y, b.x, b.y);
}
__device__ __forceinline__ uint2 f4toh4(float4 v) {
    uint2 o;
    *(__half2*)&o.x = __floats2half2_rn(v.x, v.y);
    *(__half2*)&o.y = __floats2half2_rn(v.z, v.w);
    return o;
}

// ---------------- misc small kernels ----------------
__global__ void conv_w(const float* __restrict__ src, __half* __restrict__ dst, int n) {
    int i = blockIdx.x * blockDim.x + threadIdx.x;
    if (i < n / 2) {
        float2 v = ((const float2*)src)[i];
        ((__half2*)dst)[i] = __floats2half2_rn(v.x, v.y);
    }
}

__global__ void copy_h(const float* __restrict__ f) {
    int i = blockIdx.x * blockDim.x + threadIdx.x;
    if (i < NN * (DD / 4)) {
        float4 v = ((const float4*)f)[i];
        ((uint2*)g_h_h)[i] = f4toh4(v);
    }
}

__global__ void zero_deg() {
    int i = blockIdx.x * blockDim.x + threadIdx.x;
    if (i < NN) g_deg[i] = 0;
}

__global__ void count_deg(const int* __restrict__ dst) {
    int e = blockIdx.x * blockDim.x + threadIdx.x;
    if (e < NE) atomicAdd(&g_deg[dst[e]], 1);
}

// ---- multi-block scan: 49 blocks x 1024 ----
__global__ void scan1() {
    __shared__ int wsum[32];
    int tid = threadIdx.x;
    int i = blockIdx.x * 1024 + tid;
    int v = (i < NN) ? g_deg[i] : 0;
    int x = v;
    #pragma unroll
    for (int o = 1; o < 32; o <<= 1) {
        int y = __shfl_up_sync(0xffffffffu, x, o);
        if ((tid & 31) >= o) x += y;
    }
    if ((tid & 31) == 31) wsum[tid >> 5] = x;
    __syncthreads();
    if (tid < 32) {
        int wv = wsum[tid];
        int xs = wv;
        #pragma unroll
        for (int o = 1; o < 32; o <<= 1) {
            int y = __shfl_up_sync(0xffffffffu, xs, o);
            if (tid >= o) xs += y;
        }
        wsum[tid] = xs - wv;
    }
    __syncthreads();
    int excl = (x - v) + wsum[tid >> 5];
    if (i < NN) g_indptr[i] = excl;
    if (tid == 1023) g_bsum[blockIdx.x] = excl + v;
}

__global__ void scan2() {
    int s = 0;
    for (int b = 0; b < 49; b++) { int t = g_bsum[b]; g_bsum[b] = s; s += t; }
    g_indptr[NN] = s;
}

__global__ void scan3() {
    int i = blockIdx.x * 1024 + threadIdx.x;
    if (i < NN) {
        int v = g_indptr[i] + g_bsum[blockIdx.x];
        g_indptr[i] = v;
        g_cursor[i] = v;
    }
}

// build CSR-ordered packed edges + inverse position map
__global__ void build_eids(const int* __restrict__ src, const int* __restrict__ dst,
                           const int* __restrict__ et) {
    int e = blockIdx.x * blockDim.x + threadIdx.x;
    if (e < NE) {
        int p = atomicAdd(&g_cursor[dst[e]], 1);
        g_pk[p] = src[e] | (et[e] << 16);
        g_epos[e] = p;
    }
}

// ---------------- FP16 tensor-core GEMM (K=128) ----------------
#define S2 68
#define TILE_H2 (128 * S2)

__device__ __forceinline__ void gemm_body(
    const __half* __restrict__ A, const __half* __restrict__ Bw,
    const float* __restrict__ bias, __half* __restrict__ C,
    int outDim, int rowBase, int colBase, __half2* As2, __half2* Bs2)
{
    const int tid = threadIdx.x;
    const int lane = tid & 31, wid = tid >> 5;
    const int wm = wid >> 2, wn = wid & 3;
    const int g8 = lane >> 2, t4 = lane & 3;

    float c[4][4][4];
    #pragma unroll
    for (int mt = 0; mt < 4; mt++)
        #pragma unroll
        for (int nt = 0; nt < 4; nt++)
            #pragma unroll
            for (int i = 0; i < 4; i++) c[mt][nt][i] = 0.f;

    const int lr = tid >> 1;
    const int lh2 = (tid & 1) * 16;
    const int ga = rowBase + lr;
    const int aBytes = (ga < NN) ? 16 : 0;
    const __half* Ap = A + (size_t)ga * 128;
    const __half* Bp = Bw + (size_t)(colBase + lr) * 128;
    const unsigned aDst = (unsigned)__cvta_generic_to_shared(&As2[lr * S2 + lh2]);
    const unsigned bDst = (unsigned)__cvta_generic_to_shared(&Bs2[lr * S2 + lh2]);

    #pragma unroll
    for (int ch = 0; ch < 2; ch++) {
        #pragma unroll
        for (int i = 0; i < 4; i++) {
            asm volatile("cp.async.cg.shared.global [%0], [%1], 16, %2;"
                :: "r"(aDst + ch * 128 + i * 16),
                   "l"(Ap + ch * 64 + lh2 * 2 + i * 8), "r"(aBytes));
            asm volatile("cp.async.cg.shared.global [%0], [%1], 16;"
                :: "r"(bDst + ch * 128 + i * 16),
                   "l"(Bp + ch * 64 + lh2 * 2 + i * 8));
        }
        asm volatile("cp.async.commit_group;");
    }

    #pragma unroll
    for (int ch = 0; ch < 2; ch++) {
        if (ch == 0) asm volatile("cp.async.wait_group 1;");
        else         asm volatile("cp.async.wait_group 0;");
        __syncthreads();
        #pragma unroll
        for (int ks = 0; ks < 4; ks++) {
            const int kb = ch * 32 + ks * 8;
            unsigned af[4][4], bf[4][2];
            #pragma unroll
            for (int mt = 0; mt < 4; mt++) {
                int r0 = wm * 64 + mt * 16 + g8;
                af[mt][0] = *(unsigned*)&As2[r0 * S2 + kb + t4];
                af[mt][1] = *(unsigned*)&As2[(r0 + 8) * S2 + kb + t4];
                af[mt][2] = *(unsigned*)&As2[r0 * S2 + kb + 4 + t4];
                af[mt][3] = *(unsigned*)&As2[(r0 + 8) * S2 + kb + 4 + t4];
            }
            #pragma unroll
            for (int nt = 0; nt < 4; nt++) {
                int n0 = wn * 32 + nt * 8 + g8;
                bf[nt][0] = *(unsigned*)&Bs2[n0 * S2 + kb + t4];
                bf[nt][1] = *(unsigned*)&Bs2[n0 * S2 + kb + 4 + t4];
            }
            #pragma unroll
            for (int mt = 0; mt < 4; mt++)
                #pragma unroll
                for (int nt = 0; nt < 4; nt++) {
                    asm volatile(
                        "mma.sync.aligned.m16n8k16.row.col.f32.f16.f16.f32 "
                        "{%0,%1,%2,%3}, {%4,%5,%6,%7}, {%8,%9}, {%0,%1,%2,%3};\n"
                        : "+f"(c[mt][nt][0]), "+f"(c[mt][nt][1]),
                          "+f"(c[mt][nt][2]), "+f"(c[mt][nt][3])
                        : "r"(af[mt][0]), "r"(af[mt][1]), "r"(af[mt][2]), "r"(af[mt][3]),
                          "r"(bf[nt][0]), "r"(bf[nt][1]));
                }
        }
    }

    #pragma unroll
    for (int mt = 0; mt < 4; mt++) {
        int r0 = rowBase + wm * 64 + mt * 16 + g8;
        #pragma unroll
        for (int nt = 0; nt < 4; nt++) {
            int col = colBase + wn * 32 + nt * 8 + 2 * t4;
            float b0 = bias ? bias[col] : 0.f;
            float b1 = bias ? bias[col + 1] : 0.f;
            if (r0 < NN)
                *(__half2*)(C + (size_t)r0 * outDim + col) =
                    __floats2half2_rn(c[mt][nt][0] + b0, c[mt][nt][1] + b1);
            if (r0 + 8 < NN)
                *(__half2*)(C + (size_t)(r0 + 8) * outDim + col) =
                    __floats2half2_rn(c[mt][nt][2] + b0, c[mt][nt][3] + b1);
        }
    }
}

// mode 0: fused et (y<4 -> g_t_h) + hh (y>=4 -> g_gh_h), A = g_h_h
// mode 1: gi (A = g_a_h, C = g_gi_h)
// mode 2: zft (A = g_h_h, C = g_zft_h, no bias)
__global__ __launch_bounds__(256, 2)
void gemm_all(int mode, const float* __restrict__ b0, const float* __restrict__ b1) {
    extern __shared__ __half2 sm2[];
    __half2* As2 = sm2;
    __half2* Bs2 = sm2 + TILE_H2;
    int y = blockIdx.y;
    const __half* A; const __half* Bw; const float* bias; __half* C;
    int outDim, colBase;
    if (mode == 0) {
        A = g_h_h;
        if (y < 4) { Bw = g_Wet_h; bias = b0; C = g_t_h;  outDim = 512; colBase = y * 128; }
        else       { Bw = g_Whh_h; bias = b1; C = g_gh_h; outDim = 384; colBase = (y - 4) * 128; }
    } else if (mode == 1) {
        A = g_a_h; Bw = g_Wih_h; bias = b0; C = g_gi_h; outDim = 384; colBase = y * 128;
    } else {
        A = g_h_h; Bw = g_Wfc_h; bias = nullptr; C = g_zft_h; outDim = 256; colBase = y * 128;
    }
    gemm_body(A, Bw, bias, C, outDim, blockIdx.x * 128, colBase, As2, Bs2);
}

// ---------------- message aggregation (contiguous packed edges) ----------------
__global__ void aggregate(int) {
    int w = (blockIdx.x * blockDim.x + threadIdx.x) >> 5;
    if (w >= NN) return;
    int lane = threadIdx.x & 31;
    int s0 = g_indptr[w], s1 = g_indptr[w + 1];
    float4 acc = make_float4(0.f, 0.f, 0.f, 0.f);
    for (int p = s0; p < s1; p++) {
        int pk = g_pk[p];
        int s = pk & 0xffff;
        int k = pk >> 16;
        uint2 v = ((const uint2*)(g_t_h + (size_t)s * (NET * DD) + k * DD))[lane];
        float4 f = h4tof4(v);
        acc.x += f.x; acc.y += f.y; acc.z += f.z; acc.w += f.w;
    }
    ((uint2*)(g_a_h + (size_t)w * DD))[lane] = f4toh4(acc);
}

// ---------------- GRU elementwise update (fp16 everything) ----------------
__global__ void gru_update() {
    int idx = blockIdx.x * blockDim.x + threadIdx.x;
    if (idx >= NN * 32) return;
    int n = idx >> 5, q = idx & 31;
    const __half* gip = g_gi_h + (size_t)n * 384 + q * 4;
    const __half* ghp = g_gh_h + (size_t)n * 384 + q * 4;
    float4 ir = h4tof4(*(const uint2*)gip);
    float4 iz = h4tof4(*(const uint2*)(gip + 128));
    float4 inn = h4tof4(*(const uint2*)(gip + 256));
    float4 hr = h4tof4(*(const uint2*)ghp);
    float4 hz = h4tof4(*(const uint2*)(ghp + 128));
    float4 hn = h4tof4(*(const uint2*)(ghp + 256));
    uint2* hp = (uint2*)(g_h_h + (size_t)n * 128);
    float4 h = h4tof4(hp[q]);
    float4 o;
    {
        float r = sigf(ir.x + hr.x), z = sigf(iz.x + hz.x);
        float nn2 = tanhf(inn.x + r * hn.x);
        o.x = (1.f - z) * nn2 + z * h.x;
    }
    {
        float r = sigf(ir.y + hr.y), z = sigf(iz.y + hz.y);
        float nn2 = tanhf(inn.y + r * hn.y);
        o.y = (1.f - z) * nn2 + z * h.y;
    }
    {
        float r = sigf(ir.z + hr.z), z = sigf(iz.z + hz.z);
        float nn2 = tanhf(inn.z + r * hn.z);
        o.z = (1.f - z) * nn2 + z * h.z;
    }
    {
        float r = sigf(ir.w + hr.w), z = sigf(iz.w + hz.w);
        float nn2 = tanhf(inn.w + r * hn.w);
        o.w = (1.f - z) * nn2 + z * h.w;
    }
    hp[q] = f4toh4(o);
}

// ---------------- row L2-normalize + sigmoid (fp16 h) ----------------
__global__ void norm_sigmoid() {
    int w = (blockIdx.x * blockDim.x + threadIdx.x) >> 5;
    if (w >= NN) return;
    int lane = threadIdx.x & 31;
    uint2* p = (uint2*)(g_h_h + (size_t)w * 128);
    float4 v = h4tof4(p[lane]);
    float ss = v.x * v.x + v.y * v.y + v.z * v.z + v.w * v.w;
    #pragma unroll
    for (int o = 16; o; o >>= 1) ss += __shfl_xor_sync(0xffffffffu, ss, o);
    float inv = 1.f / fmaxf(sqrtf(ss), 1e-12f);
    v.x = sigf(v.x * inv); v.y = sigf(v.y * inv);
    v.z = sigf(v.z * inv); v.w = sigf(v.w * inv);
    p[lane] = f4toh4(v);
}

// ---------------- GAT attention scalars el/er ----------------
__global__ void elr_kernel(const float* __restrict__ al, const float* __restrict__ ar) {
    int w = (blockIdx.x * blockDim.x + threadIdx.x) >> 5;
    if (w >= NN) return;
    int lane = threadIdx.x & 31;
    const uint2* z2 = (const uint2*)(g_zft_h + (size_t)w * 256);
    const float4* al4 = (const float4*)al;
    const float4* ar4 = (const float4*)ar;
    #pragma unroll
    for (int hd = 0; hd < 2; hd++) {
        float4 zv = h4tof4(z2[hd * 32 + lane]);
        float4 lv = al4[hd * 32 + lane];
        float4 rv = ar4[hd * 32 + lane];
        float pl = zv.x * lv.x + zv.y * lv.y + zv.z * lv.z + zv.w * lv.w;
        float pr = zv.x * rv.x + zv.y * rv.y + zv.z * rv.z + zv.w * rv.w;
        #pragma unroll
        for (int o = 16; o; o >>= 1) {
            pl += __shfl_xor_sync(0xffffffffu, pl, o);
            pr += __shfl_xor_sync(0xffffffffu, pr, o);
        }
        if (lane == 0) { g_el[w * 2 + hd] = pl; g_er[w * 2 + hd] = pr; }
    }
}

// ---------------- edge weights: exp(leaky(el+er)), scattered into CSR order ----------------
__global__ void edge_w(const int* __restrict__ src, const int* __restrict__ dst) {
    int e = blockIdx.x * blockDim.x + threadIdx.x;
    if (e >= NE) return;
    int s = src[e], d = dst[e];
    int p = g_epos[e];
    float2 els = ((const float2*)g_el)[s];
    float2 erd = ((const float2*)g_er)[d];
    float e0 = els.x + erd.x; e0 = e0 > 0.f ? e0 : 0.2f * e0;
    float e1 = els.y + erd.y; e1 = e1 > 0.f ? e1 : 0.2f * e1;
    ((float2*)g_wgt)[p] = make_float2(expf(e0), expf(e1));
}

// ---------------- GAT accumulation: Σ w·zft / Σ w + bias + relu ----------------
__global__ void gat_accum(const float* __restrict__ gbias) {
    int w = (blockIdx.x * blockDim.x + threadIdx.x) >> 5;
    if (w >= NN) return;
    int lane = threadIdx.x & 31;
    int s0 = g_indptr[w], s1 = g_indptr[w + 1];
    float4 a0 = make_float4(0.f,0.f,0.f,0.f), a1 = a0;
    float den0 = 0.f, den1 = 0.f;
    for (int p = s0; p < s1; p++) {
        float2 wv = ((const float2*)g_wgt)[p];
        int s = g_pk[p] & 0xffff;
        den0 += wv.x; den1 += wv.y;
        const uint2* z2 = (const uint2*)(g_zft_h + (size_t)s * 256);
        float4 z0 = h4tof4(z2[lane]), z1 = h4tof4(z2[32 + lane]);
        a0.x += wv.x * z0.x; a0.y += wv.x * z0.y; a0.z += wv.x * z0.z; a0.w += wv.x * z0.w;
        a1.x += wv.y * z1.x; a1.y += wv.y * z1.y; a1.z += wv.y * z1.z; a1.w += wv.y * z1.w;
    }
    float i0 = (den0 > 0.f) ? 1.f / den0 : 0.f;
    float i1 = (den1 > 0.f) ? 1.f / den1 : 0.f;
    const float4* b4 = (const float4*)gbias;
    float4 b0 = b4[lane], b1 = b4[32 + lane];
    float4 o0, o1;
    o0.x = fmaxf(a0.x * i0 + b0.x, 0.f); o0.y = fmaxf(a0.y * i0 + b0.y, 0.f);
    o0.z = fmaxf(a0.z * i0 + b0.z, 0.f); o0.w = fmaxf(a0.w * i0 + b0.w, 0.f);
    o1.x = fmaxf(a1.x * i1 + b1.x, 0.f); o1.y = fmaxf(a1.y * i1 + b1.y, 0.f);
    o1.z = fmaxf(a1.z * i1 + b1.z, 0.f); o1.w = fmaxf(a1.w * i1 + b1.w, 0.f);
    float4* outp = (float4*)(g_rst + (size_t)w * 256);
    outp[lane] = o0;
    outp[32 + lane] = o1;
}

// ---------------- graph bounds ----------------
__global__ void graph_bounds(const int* __restrict__ gid) {
    int b = threadIdx.x;
    if (b > NG) return;
    if (b == NG) { g_gs[NG] = NN; return; }
    int lo = 0, hi = NN;
    while (lo < hi) {
        int mid = (lo + hi) >> 1;
        if (gid[mid] < b) lo = mid + 1; else hi = mid;
    }
    g_gs[b] = lo;
}

// ---------------- mean pool + classify ----------------
__global__ void pool_classify(const float* __restrict__ Wc, const float* __restrict__ bc, int gidx) {
    __shared__ float sh[256];
    int b = blockIdx.x;
    int t = threadIdx.x;
    int s = g_gs[b], e2 = g_gs[b + 1];
    float sum = 0.f;
    for (int r = s; r < e2; r++) sum += g_rst[(size_t)r * 256 + t];
    sh[t] = sum / fmaxf((float)(e2 - s), 1.f);
    __syncthreads();
    if (t < 64) {
        int hd = t >> 5, c = t & 31;
        float acc = bc[c];
        const float* hp = sh + hd * 128;
        const float* wp = Wc + c * 128;
        #pragma unroll 8
        for (int d2 = 0; d2 < 128; d2++) acc += hp[d2] * wp[d2];
        g_logits[gidx][(b * 2 + hd) * 32 + c] = acc;
    }
}

// ---------------- final distance + head softmax ----------------
__global__ void final_kernel(float* __restrict__ out) {
    int b = threadIdx.x;
    if (b >= NG) return;
    float dv[2];
    #pragma unroll
    for (int hd = 0; hd < 2; hd++) {
        float ss = 0.f;
        #pragma unroll
        for (int c = 0; c < 32; c++) {
            float df = g_logits[0][(b * 2 + hd) * 32 + c]
                     - g_logits[1][(b * 2 + hd) * 32 + c] + 1e-6f;
            ss += df * df;
        }
        dv[hd] = sqrtf(ss);
    }
    float mx = fmaxf(dv[0], dv[1]);
    float e0 = expf(dv[0] - mx), e1 = expf(dv[1] - mx);
    float inv = 1.f / (e0 + e1);
    out[b * 2] = e0 * inv;
    out[b * 2 + 1] = e1 * inv;
}

// ---------------- host driver ----------------
extern "C" void kernel_launch(void* const* d_in, const int* in_sizes, int n_in,
                              void* d_out, int out_size) {
    const float* in1  = (const float*)d_in[0];
    const float* in2  = (const float*)d_in[1];
    const int* src1 = (const int*)d_in[2];
    const int* dst1 = (const int*)d_in[3];
    const int* et1  = (const int*)d_in[4];
    const int* gid1 = (const int*)d_in[5];
    const int* src2 = (const int*)d_in[6];
    const int* dst2 = (const int*)d_in[7];
    const int* et2  = (const int*)d_in[8];
    const int* gid2 = (const int*)d_in[9];
    const float* W_et  = (const float*)d_in[10];
    const float* b_et  = (const float*)d_in[11];
    const float* W_ih  = (const float*)d_in[12];
    const float* W_hh  = (const float*)d_in[13];
    const float* b_ih  = (const float*)d_in[14];
    const float* b_hh  = (const float*)d_in[15];
    const float* W_fc  = (const float*)d_in[16];
    const float* al    = (const float*)d_in[17];
    const float* ar    = (const float*)d_in[18];
    const float* gb    = (const float*)d_in[19];
    const float* W_cls = (const float*)d_in[20];
    const float* b_cls = (const float*)d_in[21];

    const int SMEM = 2 * TILE_H2 * 4;
    static int attr_done = 0;
    if (!attr_done) {
        cudaFuncSetAttribute(gemm_all, cudaFuncAttributeMaxDynamicSharedMemorySize, SMEM);
        attr_done = 1;
    }

    {
        __half* p0; cudaGetSymbolAddress((void**)&p0, g_Wet_h);
        __half* p1; cudaGetSymbolAddress((void**)&p1, g_Whh_h);
        __half* p2; cudaGetSymbolAddress((void**)&p2, g_Wih_h);
        __half* p3; cudaGetSymbolAddress((void**)&p3, g_Wfc_h);
        conv_w<<<(NET * DD * DD / 2 + 255) / 256, 256>>>(W_et, p0, NET * DD * DD);
        conv_w<<<(3 * DD * DD / 2 + 255) / 256, 256>>>(W_hh, p1, 3 * DD * DD);
        conv_w<<<(3 * DD * DD / 2 + 255) / 256, 256>>>(W_ih, p2, 3 * DD * DD);
        conv_w<<<(NHEADS * DD * DD / 2 + 255) / 256, 256>>>(W_fc, p3, NHEADS * DD * DD);
    }

    const int NBLK_E = (NE + 255) / 256;
    const int NBLK_N = (NN + 255) / 256;
    const int NBLK_W = NN / 8;
    const dim3 gFused(391, 7), gGI(391, 3), gZ(391, 2);

    for (int g = 0; g < 2; g++) {
        const float* feat = g ? in2 : in1;
        const int* src = g ? src2 : src1;
        const int* dst = g ? dst2 : dst1;
        const int* et  = g ? et2 : et1;
        const int* gid = g ? gid2 : gid1;

        copy_h<<<(NN * 32 + 255) / 256, 256>>>(feat);
        zero_deg<<<NBLK_N, 256>>>();
        count_deg<<<NBLK_E, 256>>>(dst);
        scan1<<<49, 1024>>>();
        scan2<<<1, 1>>>();
        scan3<<<49, 1024>>>();
        build_eids<<<NBLK_E, 256>>>(src, dst, et);

        for (int s = 0; s < NSTEPS; s++) {
            gemm_all<<<gFused, 256, SMEM>>>(0, b_et, b_hh);
            aggregate<<<NBLK_W, 256>>>(0);
            gemm_all<<<gGI, 256, SMEM>>>(1, b_ih, nullptr);
            gru_update<<<(NN * 32 + 255) / 256, 256>>>();
        }
        norm_sigmoid<<<NBLK_W, 256>>>();
        gemm_all<<<gZ, 256, SMEM>>>(2, nullptr, nullptr);
        elr_kernel<<<NBLK_W, 256>>>(al, ar);
        edge_w<<<NBLK_E, 256>>>(src, dst);
        gat_accum<<<NBLK_W, 256>>>(gb);
        graph_bounds<<<1, NG + 1>>>(gid);
        pool_classify<<<NG, 256>>>(W_cls, b_cls, g);
    }
    final_kernel<<<1, NG>>>((float*)d_out);
}

// round 9
// speedup vs baseline: 1.2515x; 1.0919x over previous
#include <cuda_runtime.h>
#include <cuda_fp16.h>
#include <math.h>
#include <float.h>

// ---------------- problem constants ----------------
#define NN      50000
#define NE      600000
#define DD      128
#define NET     4
#define NSTEPS  5
#define NHEADS  2
#define NG      64
#define NCLS    32

// ---------------- device scratch (duplicated per graph for stream overlap) ----------------
__device__ __half g_h_h [2][NN * DD];
__device__ __half g_a_h [2][NN * DD];
__device__ __half g_t_h [2][(size_t)NN * NET * DD];
__device__ __half g_gh_h[2][NN * 3 * DD];
__device__ __half g_gi_h[2][NN * 3 * DD];
__device__ __half g_zft_h[2][NN * NHEADS * DD];
__device__ float  g_el  [2][NN * NHEADS];
__device__ float  g_er  [2][NN * NHEADS];
__device__ float  g_wgt [2][NE * NHEADS];
__device__ float  g_rst [2][NN * NHEADS * DD];
__device__ float  g_logits[2][NG * NHEADS * NCLS];

// fp16 weights (shared, converted once per launch before fork)
__device__ __half g_Wet_h[NET * DD * DD];
__device__ __half g_Whh_h[3 * DD * DD];
__device__ __half g_Wih_h[3 * DD * DD];
__device__ __half g_Wfc_h[NHEADS * DD * DD];

__device__ int g_deg   [2][NN];
__device__ int g_indptr[2][NN + 1];
__device__ int g_cursor[2][NN];
__device__ int g_pk    [2][NE];
__device__ int g_epos  [2][NE];
__device__ int g_gs    [2][NG + 1];
__device__ int g_bsum  [2][64];

__device__ __forceinline__ float sigf(float x) { return 1.f / (1.f + expf(-x)); }

__device__ __forceinline__ float4 h4tof4(uint2 v) {
    float2 a = __half22float2(*(__half2*)&v.x);
    float2 b = __half22float2(*(__half2*)&v.y);
    return make_float4(a.x, a.y, b.x, b.y);
}
__device__ __forceinline__ uint2 f4toh4(float4 v) {
    uint2 o;
    *(__half2*)&o.x = __floats2half2_rn(v.x, v.y);
    *(__half2*)&o.y = __floats2half2_rn(v.z, v.w);
    return o;
}

// ---------------- misc small kernels ----------------
__global__ void conv_w(const float* __restrict__ src, __half* __restrict__ dst, int n) {
    int i = blockIdx.x * blockDim.x + threadIdx.x;
    if (i < n / 2) {
        float2 v = ((const float2*)src)[i];
        ((__half2*)dst)[i] = __floats2half2_rn(v.x, v.y);
    }
}

__global__ void copy_h(int g, const float* __restrict__ f) {
    int i = blockIdx.x * blockDim.x + threadIdx.x;
    if (i < NN * (DD / 4)) {
        float4 v = ((const float4*)f)[i];
        ((uint2*)g_h_h[g])[i] = f4toh4(v);
    }
}

__global__ void zero_deg(int g) {
    int i = blockIdx.x * blockDim.x + threadIdx.x;
    if (i < NN) g_deg[g][i] = 0;
}

__global__ void count_deg(int g, const int* __restrict__ dst) {
    int e = blockIdx.x * blockDim.x + threadIdx.x;
    if (e < NE) atomicAdd(&g_deg[g][dst[e]], 1);
}

// ---- multi-block scan: 49 blocks x 1024 ----
__global__ void scan1(int g) {
    __shared__ int wsum[32];
    int tid = threadIdx.x;
    int i = blockIdx.x * 1024 + tid;
    int v = (i < NN) ? g_deg[g][i] : 0;
    int x = v;
    #pragma unroll
    for (int o = 1; o < 32; o <<= 1) {
        int y = __shfl_up_sync(0xffffffffu, x, o);
        if ((tid & 31) >= o) x += y;
    }
    if ((tid & 31) == 31) wsum[tid >> 5] = x;
    __syncthreads();
    if (tid < 32) {
        int wv = wsum[tid];
        int xs = wv;
        #pragma unroll
        for (int o = 1; o < 32; o <<= 1) {
            int y = __shfl_up_sync(0xffffffffu, xs, o);
            if (tid >= o) xs += y;
        }
        wsum[tid] = xs - wv;
    }
    __syncthreads();
    int excl = (x - v) + wsum[tid >> 5];
    if (i < NN) g_indptr[g][i] = excl;
    if (tid == 1023) g_bsum[g][blockIdx.x] = excl + v;
}

__global__ void scan2(int g) {
    int s = 0;
    for (int b = 0; b < 49; b++) { int t = g_bsum[g][b]; g_bsum[g][b] = s; s += t; }
    g_indptr[g][NN] = s;
}

__global__ void scan3(int g) {
    int i = blockIdx.x * 1024 + threadIdx.x;
    if (i < NN) {
        int v = g_indptr[g][i] + g_bsum[g][blockIdx.x];
        g_indptr[g][i] = v;
        g_cursor[g][i] = v;
    }
}

__global__ void build_eids(int g, const int* __restrict__ src, const int* __restrict__ dst,
                           const int* __restrict__ et) {
    int e = blockIdx.x * blockDim.x + threadIdx.x;
    if (e < NE) {
        int p = atomicAdd(&g_cursor[g][dst[e]], 1);
        g_pk[g][p] = src[e] | (et[e] << 16);
        g_epos[g][e] = p;
    }
}

// ---------------- FP16 tensor-core GEMM (K=128) ----------------
#define S2 68
#define TILE_H2 (128 * S2)

__device__ __forceinline__ void gemm_body(
    const __half* __restrict__ A, const __half* __restrict__ Bw,
    const float* __restrict__ bias, __half* __restrict__ C,
    int outDim, int rowBase, int colBase, __half2* As2, __half2* Bs2)
{
    const int tid = threadIdx.x;
    const int lane = tid & 31, wid = tid >> 5;
    const int wm = wid >> 2, wn = wid & 3;
    const int g8 = lane >> 2, t4 = lane & 3;

    float c[4][4][4];
    #pragma unroll
    for (int mt = 0; mt < 4; mt++)
        #pragma unroll
        for (int nt = 0; nt < 4; nt++)
            #pragma unroll
            for (int i = 0; i < 4; i++) c[mt][nt][i] = 0.f;

    const int lr = tid >> 1;
    const int lh2 = (tid & 1) * 16;
    const int ga = rowBase + lr;
    const int aBytes = (ga < NN) ? 16 : 0;
    const __half* Ap = A + (size_t)ga * 128;
    const __half* Bp = Bw + (size_t)(colBase + lr) * 128;
    const unsigned aDst = (unsigned)__cvta_generic_to_shared(&As2[lr * S2 + lh2]);
    const unsigned bDst = (unsigned)__cvta_generic_to_shared(&Bs2[lr * S2 + lh2]);

    #pragma unroll
    for (int ch = 0; ch < 2; ch++) {
        #pragma unroll
        for (int i = 0; i < 4; i++) {
            asm volatile("cp.async.cg.shared.global [%0], [%1], 16, %2;"
                :: "r"(aDst + ch * 128 + i * 16),
                   "l"(Ap + ch * 64 + lh2 * 2 + i * 8), "r"(aBytes));
            asm volatile("cp.async.cg.shared.global [%0], [%1], 16;"
                :: "r"(bDst + ch * 128 + i * 16),
                   "l"(Bp + ch * 64 + lh2 * 2 + i * 8));
        }
        asm volatile("cp.async.commit_group;");
    }

    #pragma unroll
    for (int ch = 0; ch < 2; ch++) {
        if (ch == 0) asm volatile("cp.async.wait_group 1;");
        else         asm volatile("cp.async.wait_group 0;");
        __syncthreads();
        #pragma unroll
        for (int ks = 0; ks < 4; ks++) {
            const int kb = ch * 32 + ks * 8;
            unsigned af[4][4], bf[4][2];
            #pragma unroll
            for (int mt = 0; mt < 4; mt++) {
                int r0 = wm * 64 + mt * 16 + g8;
                af[mt][0] = *(unsigned*)&As2[r0 * S2 + kb + t4];
                af[mt][1] = *(unsigned*)&As2[(r0 + 8) * S2 + kb + t4];
                af[mt][2] = *(unsigned*)&As2[r0 * S2 + kb + 4 + t4];
                af[mt][3] = *(unsigned*)&As2[(r0 + 8) * S2 + kb + 4 + t4];
            }
            #pragma unroll
            for (int nt = 0; nt < 4; nt++) {
                int n0 = wn * 32 + nt * 8 + g8;
                bf[nt][0] = *(unsigned*)&Bs2[n0 * S2 + kb + t4];
                bf[nt][1] = *(unsigned*)&Bs2[n0 * S2 + kb + 4 + t4];
            }
            #pragma unroll
            for (int mt = 0; mt < 4; mt++)
                #pragma unroll
                for (int nt = 0; nt < 4; nt++) {
                    asm volatile(
                        "mma.sync.aligned.m16n8k16.row.col.f32.f16.f16.f32 "
                        "{%0,%1,%2,%3}, {%4,%5,%6,%7}, {%8,%9}, {%0,%1,%2,%3};\n"
                        : "+f"(c[mt][nt][0]), "+f"(c[mt][nt][1]),
                          "+f"(c[mt][nt][2]), "+f"(c[mt][nt][3])
                        : "r"(af[mt][0]), "r"(af[mt][1]), "r"(af[mt][2]), "r"(af[mt][3]),
                          "r"(bf[nt][0]), "r"(bf[nt][1]));
                }
        }
    }

    #pragma unroll
    for (int mt = 0; mt < 4; mt++) {
        int r0 = rowBase + wm * 64 + mt * 16 + g8;
        #pragma unroll
        for (int nt = 0; nt < 4; nt++) {
            int col = colBase + wn * 32 + nt * 8 + 2 * t4;
            float b0 = bias ? bias[col] : 0.f;
            float b1 = bias ? bias[col + 1] : 0.f;
            if (r0 < NN)
                *(__half2*)(C + (size_t)r0 * outDim + col) =
                    __floats2half2_rn(c[mt][nt][0] + b0, c[mt][nt][1] + b1);
            if (r0 + 8 < NN)
                *(__half2*)(C + (size_t)(r0 + 8) * outDim + col) =
                    __floats2half2_rn(c[mt][nt][2] + b0, c[mt][nt][3] + b1);
        }
    }
}

// mode 0: fused et (y<4 -> t) + hh (y>=4 -> gh), A = h
// mode 1: gi (A = a, C = gi)
// mode 2: zft (A = h, C = zft, no bias)
__global__ __launch_bounds__(256, 2)
void gemm_all(int mode, int g, const float* __restrict__ b0, const float* __restrict__ b1) {
    extern __shared__ __half2 sm2[];
    __half2* As2 = sm2;
    __half2* Bs2 = sm2 + TILE_H2;
    int y = blockIdx.y;
    const __half* A; const __half* Bw; const float* bias; __half* C;
    int outDim, colBase;
    if (mode == 0) {
        A = g_h_h[g];
        if (y < 4) { Bw = g_Wet_h; bias = b0; C = g_t_h[g];  outDim = 512; colBase = y * 128; }
        else       { Bw = g_Whh_h; bias = b1; C = g_gh_h[g]; outDim = 384; colBase = (y - 4) * 128; }
    } else if (mode == 1) {
        A = g_a_h[g]; Bw = g_Wih_h; bias = b0; C = g_gi_h[g]; outDim = 384; colBase = y * 128;
    } else {
        A = g_h_h[g]; Bw = g_Wfc_h; bias = nullptr; C = g_zft_h[g]; outDim = 256; colBase = y * 128;
    }
    gemm_body(A, Bw, bias, C, outDim, blockIdx.x * 128, colBase, As2, Bs2);
}

// ---------------- message aggregation (prefetched packed edges) ----------------
__global__ void aggregate(int g) {
    int w = (blockIdx.x * blockDim.x + threadIdx.x) >> 5;
    if (w >= NN) return;
    int lane = threadIdx.x & 31;
    int s0 = g_indptr[g][w], s1 = g_indptr[g][w + 1];
    const int* pkp = g_pk[g];
    const __half* tb = g_t_h[g];
    float4 acc = make_float4(0.f, 0.f, 0.f, 0.f);
    int pk = (s0 < s1) ? pkp[s0] : 0;
    for (int p = s0; p < s1; p++) {
        int pk2 = (p + 1 < s1) ? pkp[p + 1] : 0;
        int s = pk & 0xffff;
        int k = pk >> 16;
        uint2 v = ((const uint2*)(tb + (size_t)s * (NET * DD) + k * DD))[lane];
        float4 f = h4tof4(v);
        acc.x += f.x; acc.y += f.y; acc.z += f.z; acc.w += f.w;
        pk = pk2;
    }
    ((uint2*)(g_a_h[g] + (size_t)w * DD))[lane] = f4toh4(acc);
}

// ---------------- GRU elementwise update ----------------
__global__ void gru_update(int g) {
    int idx = blockIdx.x * blockDim.x + threadIdx.x;
    if (idx >= NN * 32) return;
    int n = idx >> 5, q = idx & 31;
    const __half* gip = g_gi_h[g] + (size_t)n * 384 + q * 4;
    const __half* ghp = g_gh_h[g] + (size_t)n * 384 + q * 4;
    float4 ir = h4tof4(*(const uint2*)gip);
    float4 iz = h4tof4(*(const uint2*)(gip + 128));
    float4 inn = h4tof4(*(const uint2*)(gip + 256));
    float4 hr = h4tof4(*(const uint2*)ghp);
    float4 hz = h4tof4(*(const uint2*)(ghp + 128));
    float4 hn = h4tof4(*(const uint2*)(ghp + 256));
    uint2* hp = (uint2*)(g_h_h[g] + (size_t)n * 128);
    float4 h = h4tof4(hp[q]);
    float4 o;
    {
        float r = sigf(ir.x + hr.x), z = sigf(iz.x + hz.x);
        float nn2 = tanhf(inn.x + r * hn.x);
        o.x = (1.f - z) * nn2 + z * h.x;
    }
    {
        float r = sigf(ir.y + hr.y), z = sigf(iz.y + hz.y);
        float nn2 = tanhf(inn.y + r * hn.y);
        o.y = (1.f - z) * nn2 + z * h.y;
    }
    {
        float r = sigf(ir.z + hr.z), z = sigf(iz.z + hz.z);
        float nn2 = tanhf(inn.z + r * hn.z);
        o.z = (1.f - z) * nn2 + z * h.z;
    }
    {
        float r = sigf(ir.w + hr.w), z = sigf(iz.w + hz.w);
        float nn2 = tanhf(inn.w + r * hn.w);
        o.w = (1.f - z) * nn2 + z * h.w;
    }
    hp[q] = f4toh4(o);
}

// ---------------- row L2-normalize + sigmoid ----------------
__global__ void norm_sigmoid(int g) {
    int w = (blockIdx.x * blockDim.x + threadIdx.x) >> 5;
    if (w >= NN) return;
    int lane = threadIdx.x & 31;
    uint2* p = (uint2*)(g_h_h[g] + (size_t)w * 128);
    float4 v = h4tof4(p[lane]);
    float ss = v.x * v.x + v.y * v.y + v.z * v.z + v.w * v.w;
    #pragma unroll
    for (int o = 16; o; o >>= 1) ss += __shfl_xor_sync(0xffffffffu, ss, o);
    float inv = 1.f / fmaxf(sqrtf(ss), 1e-12f);
    v.x = sigf(v.x * inv); v.y = sigf(v.y * inv);
    v.z = sigf(v.z * inv); v.w = sigf(v.w * inv);
    p[lane] = f4toh4(v);
}

// ---------------- GAT attention scalars el/er ----------------
__global__ void elr_kernel(int g, const float* __restrict__ al, const float* __restrict__ ar) {
    int w = (blockIdx.x * blockDim.x + threadIdx.x) >> 5;
    if (w >= NN) return;
    int lane = threadIdx.x & 31;
    const uint2* z2 = (const uint2*)(g_zft_h[g] + (size_t)w * 256);
    const float4* al4 = (const float4*)al;
    const float4* ar4 = (const float4*)ar;
    #pragma unroll
    for (int hd = 0; hd < 2; hd++) {
        float4 zv = h4tof4(z2[hd * 32 + lane]);
        float4 lv = al4[hd * 32 + lane];
        float4 rv = ar4[hd * 32 + lane];
        float pl = zv.x * lv.x + zv.y * lv.y + zv.z * lv.z + zv.w * lv.w;
        float pr = zv.x * rv.x + zv.y * rv.y + zv.z * rv.z + zv.w * rv.w;
        #pragma unroll
        for (int o = 16; o; o >>= 1) {
            pl += __shfl_xor_sync(0xffffffffu, pl, o);
            pr += __shfl_xor_sync(0xffffffffu, pr, o);
        }
        if (lane == 0) { g_el[g][w * 2 + hd] = pl; g_er[g][w * 2 + hd] = pr; }
    }
}

// ---------------- edge weights: exp(leaky(el+er)) scattered into CSR order ----------------
__global__ void edge_w(int g, const int* __restrict__ src, const int* __restrict__ dst) {
    int e = blockIdx.x * blockDim.x + threadIdx.x;
    if (e >= NE) return;
    int s = src[e], d = dst[e];
    int p = g_epos[g][e];
    float2 els = ((const float2*)g_el[g])[s];
    float2 erd = ((const float2*)g_er[g])[d];
    float e0 = els.x + erd.x; e0 = e0 > 0.f ? e0 : 0.2f * e0;
    float e1 = els.y + erd.y; e1 = e1 > 0.f ? e1 : 0.2f * e1;
    ((float2*)g_wgt[g])[p] = make_float2(expf(e0), expf(e1));
}

// ---------------- GAT accumulation: Σ w·zft / Σ w + bias + relu ----------------
__global__ void gat_accum(int g, const float* __restrict__ gbias) {
    int w = (blockIdx.x * blockDim.x + threadIdx.x) >> 5;
    if (w >= NN) return;
    int lane = threadIdx.x & 31;
    int s0 = g_indptr[g][w], s1 = g_indptr[g][w + 1];
    const int* pkp = g_pk[g];
    const float2* wp2 = (const float2*)g_wgt[g];
    const __half* zb = g_zft_h[g];
    float4 a0 = make_float4(0.f,0.f,0.f,0.f), a1 = a0;
    float den0 = 0.f, den1 = 0.f;
    int pk = (s0 < s1) ? pkp[s0] : 0;
    for (int p = s0; p < s1; p++) {
        int pk2 = (p + 1 < s1) ? pkp[p + 1] : 0;
        float2 wv = wp2[p];
        int s = pk & 0xffff;
        den0 += wv.x; den1 += wv.y;
        const uint2* z2 = (const uint2*)(zb + (size_t)s * 256);
        float4 z0 = h4tof4(z2[lane]), z1 = h4tof4(z2[32 + lane]);
        a0.x += wv.x * z0.x; a0.y += wv.x * z0.y; a0.z += wv.x * z0.z; a0.w += wv.x * z0.w;
        a1.x += wv.y * z1.x; a1.y += wv.y * z1.y; a1.z += wv.y * z1.z; a1.w += wv.y * z1.w;
        pk = pk2;
    }
    float i0 = (den0 > 0.f) ? 1.f / den0 : 0.f;
    float i1 = (den1 > 0.f) ? 1.f / den1 : 0.f;
    const float4* b4 = (const float4*)gbias;
    float4 b0 = b4[lane], b1 = b4[32 + lane];
    float4 o0, o1;
    o0.x = fmaxf(a0.x * i0 + b0.x, 0.f); o0.y = fmaxf(a0.y * i0 + b0.y, 0.f);
    o0.z = fmaxf(a0.z * i0 + b0.z, 0.f); o0.w = fmaxf(a0.w * i0 + b0.w, 0.f);
    o1.x = fmaxf(a1.x * i1 + b1.x, 0.f); o1.y = fmaxf(a1.y * i1 + b1.y, 0.f);
    o1.z = fmaxf(a1.z * i1 + b1.z, 0.f); o1.w = fmaxf(a1.w * i1 + b1.w, 0.f);
    float4* outp = (float4*)(g_rst[g] + (size_t)w * 256);
    outp[lane] = o0;
    outp[32 + lane] = o1;
}

// ---------------- graph bounds ----------------
__global__ void graph_bounds(int g, const int* __restrict__ gid) {
    int b = threadIdx.x;
    if (b > NG) return;
    if (b == NG) { g_gs[g][NG] = NN; return; }
    int lo = 0, hi = NN;
    while (lo < hi) {
        int mid = (lo + hi) >> 1;
        if (gid[mid] < b) lo = mid + 1; else hi = mid;
    }
    g_gs[g][b] = lo;
}

// ---------------- mean pool + classify ----------------
__global__ void pool_classify(int g, const float* __restrict__ Wc, const float* __restrict__ bc) {
    __shared__ float sh[256];
    int b = blockIdx.x;
    int t = threadIdx.x;
    int s = g_gs[g][b], e2 = g_gs[g][b + 1];
    float sum = 0.f;
    const float* rb = g_rst[g];
    for (int r = s; r < e2; r++) sum += rb[(size_t)r * 256 + t];
    sh[t] = sum / fmaxf((float)(e2 - s), 1.f);
    __syncthreads();
    if (t < 64) {
        int hd = t >> 5, c = t & 31;
        float acc = bc[c];
        const float* hp = sh + hd * 128;
        const float* wp = Wc + c * 128;
        #pragma unroll 8
        for (int d2 = 0; d2 < 128; d2++) acc += hp[d2] * wp[d2];
        g_logits[g][(b * 2 + hd) * 32 + c] = acc;
    }
}

// ---------------- final distance + head softmax ----------------
__global__ void final_kernel(float* __restrict__ out) {
    int b = threadIdx.x;
    if (b >= NG) return;
    float dv[2];
    #pragma unroll
    for (int hd = 0; hd < 2; hd++) {
        float ss = 0.f;
        #pragma unroll
        for (int c = 0; c < 32; c++) {
            float df = g_logits[0][(b * 2 + hd) * 32 + c]
                     - g_logits[1][(b * 2 + hd) * 32 + c] + 1e-6f;
            ss += df * df;
        }
        dv[hd] = sqrtf(ss);
    }
    float mx = fmaxf(dv[0], dv[1]);
    float e0 = expf(dv[0] - mx), e1 = expf(dv[1] - mx);
    float inv = 1.f / (e0 + e1);
    out[b * 2] = e0 * inv;
    out[b * 2 + 1] = e1 * inv;
}

// ---------------- host driver ----------------
extern "C" void kernel_launch(void* const* d_in, const int* in_sizes, int n_in,
                              void* d_out, int out_size) {
    const float* in1  = (const float*)d_in[0];
    const float* in2  = (const float*)d_in[1];
    const int* srcA[2] = { (const int*)d_in[2], (const int*)d_in[6] };
    const int* dstA[2] = { (const int*)d_in[3], (const int*)d_in[7] };
    const int* etA [2] = { (const int*)d_in[4], (const int*)d_in[8] };
    const int* gidA[2] = { (const int*)d_in[5], (const int*)d_in[9] };
    const float* featA[2] = { in1, in2 };
    const float* W_et  = (const float*)d_in[10];
    const float* b_et  = (const float*)d_in[11];
    const float* W_ih  = (const float*)d_in[12];
    const float* W_hh  = (const float*)d_in[13];
    const float* b_ih  = (const float*)d_in[14];
    const float* b_hh  = (const float*)d_in[15];
    const float* W_fc  = (const float*)d_in[16];
    const float* al    = (const float*)d_in[17];
    const float* ar    = (const float*)d_in[18];
    const float* gb    = (const float*)d_in[19];
    const float* W_cls = (const float*)d_in[20];
    const float* b_cls = (const float*)d_in[21];

    const int SMEM = 2 * TILE_H2 * 4;
    static int init_done = 0;
    static cudaStream_t st[2];
    static cudaEvent_t evRoot, evDone[2];
    if (!init_done) {
        cudaFuncSetAttribute(gemm_all, cudaFuncAttributeMaxDynamicSharedMemorySize, SMEM);
        cudaStreamCreateWithFlags(&st[0], cudaStreamNonBlocking);
        cudaStreamCreateWithFlags(&st[1], cudaStreamNonBlocking);
        cudaEventCreateWithFlags(&evRoot, cudaEventDisableTiming);
        cudaEventCreateWithFlags(&evDone[0], cudaEventDisableTiming);
        cudaEventCreateWithFlags(&evDone[1], cudaEventDisableTiming);
        init_done = 1;
    }

    // weight conversion on root stream (both branches depend on it)
    {
        __half* p0; cudaGetSymbolAddress((void**)&p0, g_Wet_h);
        __half* p1; cudaGetSymbolAddress((void**)&p1, g_Whh_h);
        __half* p2; cudaGetSymbolAddress((void**)&p2, g_Wih_h);
        __half* p3; cudaGetSymbolAddress((void**)&p3, g_Wfc_h);
        conv_w<<<(NET * DD * DD / 2 + 255) / 256, 256>>>(W_et, p0, NET * DD * DD);
        conv_w<<<(3 * DD * DD / 2 + 255) / 256, 256>>>(W_hh, p1, 3 * DD * DD);
        conv_w<<<(3 * DD * DD / 2 + 255) / 256, 256>>>(W_ih, p2, 3 * DD * DD);
        conv_w<<<(NHEADS * DD * DD / 2 + 255) / 256, 256>>>(W_fc, p3, NHEADS * DD * DD);
    }

    cudaEventRecord(evRoot, 0);

    const int NBLK_E = (NE + 255) / 256;
    const int NBLK_N = (NN + 255) / 256;
    const int NBLK_W = NN / 8;
    const dim3 gFused(391, 7), gGI(391, 3), gZ(391, 2);

    for (int g = 0; g < 2; g++) {
        cudaStream_t s = st[g];
        cudaStreamWaitEvent(s, evRoot, 0);
        const float* feat = featA[g];
        const int* src = srcA[g];
        const int* dst = dstA[g];
        const int* et  = etA[g];
        const int* gid = gidA[g];

        copy_h<<<(NN * 32 + 255) / 256, 256, 0, s>>>(g, feat);
        zero_deg<<<NBLK_N, 256, 0, s>>>(g);
        count_deg<<<NBLK_E, 256, 0, s>>>(g, dst);
        scan1<<<49, 1024, 0, s>>>(g);
        scan2<<<1, 1, 0, s>>>(g);
        scan3<<<49, 1024, 0, s>>>(g);
        build_eids<<<NBLK_E, 256, 0, s>>>(g, src, dst, et);

        for (int it = 0; it < NSTEPS; it++) {
            gemm_all<<<gFused, 256, SMEM, s>>>(0, g, b_et, b_hh);
            aggregate<<<NBLK_W, 256, 0, s>>>(g);
            gemm_all<<<gGI, 256, SMEM, s>>>(1, g, b_ih, nullptr);
            gru_update<<<(NN * 32 + 255) / 256, 256, 0, s>>>(g);
        }
        norm_sigmoid<<<NBLK_W, 256, 0, s>>>(g);
        gemm_all<<<gZ, 256, SMEM, s>>>(2, g, nullptr, nullptr);
        elr_kernel<<<NBLK_W, 256, 0, s>>>(g, al, ar);
        edge_w<<<NBLK_E, 256, 0, s>>>(g, src, dst);
        gat_accum<<<NBLK_W, 256, 0, s>>>(g, gb);
        graph_bounds<<<1, NG + 1, 0, s>>>(g, gid);
        pool_classify<<<NG, 256, 0, s>>>(g, W_cls, b_cls);
        cudaEventRecord(evDone[g], s);
    }

    cudaStreamWaitEvent(0, evDone[0], 0);
    cudaStreamWaitEvent(0, evDone[1], 0);
    final_kernel<<<1, NG>>>((float*)d_out);
}